// round 6
// baseline (speedup 1.0000x reference)
#include <cuda_runtime.h>
#include <cuda_bf16.h>
#include <cstdint>

// ============================================================================
// LogMM: out[16384,1024] = log( x[16384,1024] @ matrix[1024,1024] )
// (reference's big/small branches sum exactly to log(max(y,tiny)))
//
// R6: bf16 mma.sync persistent GEMM with 64x128 tiles (2048 tiles -> 1.2%
// CTA load imbalance instead of 16% with 128x128), 4-stage cp.async ring,
// 2 CTAs/SM, fused __logf epilogue overlapped with next tile's loads.
// ============================================================================

#define M_TOTAL 16384
#define N_TOTAL 1024
#define K_TOTAL 1024
#define TILE_M 64
#define TILE_N 128
#define BK 64                    // bf16 per K-chunk (128 B per row)
#define NCHUNK (K_TOTAL / BK)    // 16
#define NSTAGE 4
#define NTILES ((M_TOTAL / TILE_M) * (N_TOTAL / TILE_N))  // 2048
#define GRID_GEMM 296            // 2 CTAs/SM x 148 SMs

static constexpr int SMEM_PAD = 1024;
static constexpr int A_TILE_BYTES = TILE_M * 128;   // 8192
static constexpr int B_TILE_BYTES = TILE_N * 128;   // 16384
static constexpr int BUF_STRIDE = A_TILE_BYTES + B_TILE_BYTES;  // 24576
static constexpr int SMEM_TOTAL = SMEM_PAD + NSTAGE * BUF_STRIDE;  // 99328

// Scratch bf16 buffers (device globals: allocation-free)
__device__ __align__(256) __nv_bfloat16 g_xb[(size_t)M_TOTAL * K_TOTAL];
__device__ __align__(256) __nv_bfloat16 g_bt[(size_t)N_TOTAL * K_TOTAL];

// ---------------------------------------------------------------------------
// Helpers
// ---------------------------------------------------------------------------
__device__ __forceinline__ uint32_t smem_u32(const void* p) {
    uint32_t a;
    asm("{ .reg .u64 t; cvta.to.shared.u64 t, %1; cvt.u32.u64 %0, t; }" : "=r"(a) : "l"(p));
    return a;
}
__device__ __forceinline__ uint32_t sw128(uint32_t off) {
    return off ^ ((off >> 3) & 0x70);
}
__device__ __forceinline__ void cp_async16(uint32_t smem_addr, const void* gptr) {
    asm volatile("cp.async.cg.shared.global [%0], [%1], 16;"
                 :: "r"(smem_addr), "l"(gptr) : "memory");
}
#define CP_COMMIT() asm volatile("cp.async.commit_group;" ::: "memory")
#define CP_WAIT(n)  asm volatile("cp.async.wait_group %0;" :: "n"(n) : "memory")

__device__ __forceinline__ void ldsm_x4(uint32_t* r, uint32_t addr) {
    asm volatile("ldmatrix.sync.aligned.m8n8.x4.shared.b16 {%0, %1, %2, %3}, [%4];"
                 : "=r"(r[0]), "=r"(r[1]), "=r"(r[2]), "=r"(r[3]) : "r"(addr));
}
__device__ __forceinline__ void mma16816(float* c, const uint32_t* a, const uint32_t* b) {
    asm volatile("mma.sync.aligned.m16n8k16.row.col.f32.bf16.bf16.f32 "
                 "{%0, %1, %2, %3}, {%4, %5, %6, %7}, {%8, %9}, {%0, %1, %2, %3};"
                 : "+f"(c[0]), "+f"(c[1]), "+f"(c[2]), "+f"(c[3])
                 : "r"(a[0]), "r"(a[1]), "r"(a[2]), "r"(a[3]), "r"(b[0]), "r"(b[1]));
}
__device__ __forceinline__ uint32_t pack_bf16x2(float a, float b) {
    __nv_bfloat162 h = __floats2bfloat162_rn(a, b);
    return *reinterpret_cast<uint32_t*>(&h);
}

// ---------------------------------------------------------------------------
// Fused conversion kernel:
//   blocks [0, 8192):         x fp32 -> g_xb bf16 (8 elems/thread)
//   blocks [8192, 8192+1024): matrix[K,N] -> g_bt[N,K] bf16 (32x32 tiles)
// ---------------------------------------------------------------------------
#define CVT_X_BLOCKS (M_TOTAL * K_TOTAL / (256 * 8))   // 8192
#define CVT_T_BLOCKS ((K_TOTAL / 32) * (N_TOTAL / 32)) // 1024

__global__ void __launch_bounds__(256)
cvt_kernel(const float* __restrict__ x, const float* __restrict__ m) {
    int tid = threadIdx.x;
    if (blockIdx.x < CVT_X_BLOCKS) {
        size_t i = ((size_t)blockIdx.x * 256 + tid) * 8;
        float4 a = *reinterpret_cast<const float4*>(x + i);
        float4 b = *reinterpret_cast<const float4*>(x + i + 4);
        uint4 o;
        o.x = pack_bf16x2(a.x, a.y);
        o.y = pack_bf16x2(a.z, a.w);
        o.z = pack_bf16x2(b.x, b.y);
        o.w = pack_bf16x2(b.z, b.w);
        *reinterpret_cast<uint4*>(g_xb + i) = o;
    } else {
        __shared__ float tile[32][33];
        int t = blockIdx.x - CVT_X_BLOCKS;
        int bn = (t & 31) * 32;          // n block
        int bk = (t >> 5) * 32;          // k block
        int lane = tid & 31;
        int rr = tid >> 5;               // 0..7
#pragma unroll
        for (int i = 0; i < 4; i++) {
            int row = i * 8 + rr;        // k within tile
            tile[row][lane] = m[(size_t)(bk + row) * N_TOTAL + bn + lane];
        }
        __syncthreads();
#pragma unroll
        for (int i = 0; i < 4; i++) {
            int row = i * 8 + rr;        // n within tile
            g_bt[(size_t)(bn + row) * K_TOTAL + bk + lane] =
                __float2bfloat16_rn(tile[lane][row]);
        }
    }
}

// ---------------------------------------------------------------------------
// GEMM + log kernel (persistent, cross-tile pipelined, 64x128 tiles)
// ---------------------------------------------------------------------------
// Issue cp.asyncs for global chunk g (tile = first + (g>>4)*GRID, kc = g&15)
__device__ __forceinline__ void issue_chunk(uint32_t smem_base, int g, int first, int tid) {
    int t = first + (g >> 4) * GRID_GEMM;
    int kc = g & (NCHUNK - 1);
    int m0 = (t >> 3) * TILE_M;
    int n0 = (t & 7) * TILE_N;
    const uint4* Ag = reinterpret_cast<const uint4*>(g_xb + (size_t)m0 * K_TOTAL + kc * BK);
    const uint4* Bg = reinterpret_cast<const uint4*>(g_bt + (size_t)n0 * K_TOTAL + kc * BK);
    uint32_t Abase = smem_base + SMEM_PAD + (g % NSTAGE) * BUF_STRIDE;
    uint32_t Bbase = Abase + A_TILE_BYTES;
    // A: 64 rows x 128B = 512 chunks of 16B (2 per thread)
#pragma unroll
    for (int i = 0; i < 2; i++) {
        int cc = i * 256 + tid;
        int row = cc >> 3;                // 0..63
        int c16 = cc & 7;
        uint32_t sw = sw128((uint32_t)(row * 128 + c16 * 16));
        cp_async16(Abase + sw, Ag + (size_t)row * (K_TOTAL / 8) + c16);
    }
    // B: 128 rows x 128B = 1024 chunks (4 per thread)
#pragma unroll
    for (int i = 0; i < 4; i++) {
        int cc = i * 256 + tid;
        int row = cc >> 3;                // 0..127
        int c16 = cc & 7;
        uint32_t sw = sw128((uint32_t)(row * 128 + c16 * 16));
        cp_async16(Bbase + sw, Bg + (size_t)row * (K_TOTAL / 8) + c16);
    }
    CP_COMMIT();
}

__global__ void __launch_bounds__(256, 2)
logmm_gemm_kernel(float* __restrict__ out) {
    extern __shared__ char smem[];
    uint32_t sb = smem_u32(smem);
    int tid = threadIdx.x;
    int wid = tid >> 5;
    int lid = tid & 31;

    // 8 warps: warp_m in {0,1} (32 rows each), warp_n in {0..3} (32 cols each)
    int warp_m = wid >> 2;
    int warp_n = wid & 3;

    int first = blockIdx.x;
    int my_tiles = (NTILES - 1 - first) / GRID_GEMM + 1;  // 7 or 6
    int G = my_tiles * NCHUNK;

    float acc[2][4][4];
#pragma unroll
    for (int mf = 0; mf < 2; mf++)
#pragma unroll
        for (int nf = 0; nf < 4; nf++)
#pragma unroll
            for (int i = 0; i < 4; i++) acc[mf][nf][i] = 0.0f;

    // Prologue: fill 3 of 4 stages
    issue_chunk(sb, 0, first, tid);
    issue_chunk(sb, 1, first, tid);
    issue_chunk(sb, 2, first, tid);

    for (int g = 0; g < G; g++) {
        if (g == G - 1) { CP_WAIT(0); } else { CP_WAIT(2); }
        __syncthreads();

        // Prefetch chunk g+3 (may belong to the NEXT tile -> no drain).
        // Safe: buffer (g+3)%4 == (g-1)%4 was consumed at iter g-1; the
        // __syncthreads above guarantees all warps are past it.
        if (g + 3 < G) issue_chunk(sb, g + 3, first, tid);

        uint32_t Ab = sb + SMEM_PAD + (g % NSTAGE) * BUF_STRIDE;
        uint32_t Bb = Ab + A_TILE_BYTES;
#pragma unroll
        for (int ks = 0; ks < 4; ks++) {
            uint32_t a[2][4], b[2][4];
#pragma unroll
            for (int mf = 0; mf < 2; mf++) {
                int row = warp_m * 32 + mf * 16 + (lid & 15);
                uint32_t off = (uint32_t)(row * 128 + ks * 32 + ((lid >> 4) << 4));
                ldsm_x4(a[mf], Ab + sw128(off));
            }
#pragma unroll
            for (int p = 0; p < 2; p++) {
                int row = warp_n * 32 + p * 16 + (lid & 7) + ((lid >> 4) << 3);
                uint32_t off = (uint32_t)(row * 128 + ks * 32 + (((lid >> 3) & 1) << 4));
                ldsm_x4(b[p], Bb + sw128(off));
            }
#pragma unroll
            for (int mf = 0; mf < 2; mf++)
#pragma unroll
                for (int nf = 0; nf < 4; nf++)
                    mma16816(acc[mf][nf], a[mf], b[nf >> 1] + (nf & 1) * 2);
        }

        // Tile finished? Epilogue overlapped with in-flight next-tile loads.
        if ((g & (NCHUNK - 1)) == NCHUNK - 1) {
            int t = first + (g >> 4) * GRID_GEMM;
            int m0 = (t >> 3) * TILE_M;
            int n0 = (t & 7) * TILE_N;
#pragma unroll
            for (int mf = 0; mf < 2; mf++) {
#pragma unroll
                for (int nf = 0; nf < 4; nf++) {
                    int row0 = m0 + warp_m * 32 + mf * 16 + (lid >> 2);
                    int col = n0 + warp_n * 32 + nf * 8 + (lid & 3) * 2;
                    float2 v0, v1;
                    v0.x = __logf(fmaxf(acc[mf][nf][0], 1.17549435e-38f));
                    v0.y = __logf(fmaxf(acc[mf][nf][1], 1.17549435e-38f));
                    v1.x = __logf(fmaxf(acc[mf][nf][2], 1.17549435e-38f));
                    v1.y = __logf(fmaxf(acc[mf][nf][3], 1.17549435e-38f));
                    *reinterpret_cast<float2*>(out + (size_t)row0 * N_TOTAL + col) = v0;
                    *reinterpret_cast<float2*>(out + (size_t)(row0 + 8) * N_TOTAL + col) = v1;
                    acc[mf][nf][0] = 0.0f;
                    acc[mf][nf][1] = 0.0f;
                    acc[mf][nf][2] = 0.0f;
                    acc[mf][nf][3] = 0.0f;
                }
            }
        }
    }
}

// ---------------------------------------------------------------------------
// Launch
// ---------------------------------------------------------------------------
extern "C" void kernel_launch(void* const* d_in, const int* in_sizes, int n_in,
                              void* d_out, int out_size) {
    const float* x = (const float*)d_in[0];
    const float* mat = (const float*)d_in[1];
    if (n_in >= 2 && in_sizes[0] == N_TOTAL * K_TOTAL && in_sizes[1] == M_TOTAL * K_TOTAL) {
        const float* t = x; x = mat; mat = t;
    }
    float* out = (float*)d_out;

    cudaFuncSetAttribute(logmm_gemm_kernel,
                         cudaFuncAttributeMaxDynamicSharedMemorySize, SMEM_TOTAL);

    cvt_kernel<<<CVT_X_BLOCKS + CVT_T_BLOCKS, 256>>>(x, mat);
    logmm_gemm_kernel<<<GRID_GEMM, 256, SMEM_TOTAL>>>(out);
}

// round 7
// speedup vs baseline: 1.0642x; 1.0642x over previous
#include <cuda_runtime.h>
#include <cuda_bf16.h>
#include <cstdint>

// ============================================================================
// LogMM: out[16384,1024] = log( x[16384,1024] @ matrix[1024,1024] )
// (reference's big/small branches sum exactly to log(max(y,tiny)))
//
// R7: back to 128x128 tiles (R6's 64x128 regressed: per-chunk MMA count
// halved while B-load stayed full -> worse hiding). Persistent chunk-stream
// GEMM, 3-stage cp.async ring, 2 CTAs/SM. NEW: SM-level balanced contiguous
// tile assignment exploiting bid->smid = LUT[bid%148]: CTA b and b+148 share
// an SM, so each SM-pair gets 7 (or 6) contiguous tiles split 4/3.
// ============================================================================

#define M_TOTAL 16384
#define N_TOTAL 1024
#define K_TOTAL 1024
#define TILE_M 128
#define TILE_N 128
#define BK 64                    // bf16 per K-chunk (128 B per row)
#define NCHUNK (K_TOTAL / BK)    // 16
#define NSTAGE 3
#define NTILES ((M_TOTAL / TILE_M) * (N_TOTAL / TILE_N))  // 1024
#define NSM 148
#define GRID_GEMM (2 * NSM)      // 296

static constexpr int SMEM_PAD = 1024;
static constexpr int TILE_BYTES = TILE_M * 128;     // 16384
static constexpr int BUF_STRIDE = 2 * TILE_BYTES;   // 32768
static constexpr int SMEM_TOTAL = SMEM_PAD + NSTAGE * BUF_STRIDE;  // 99328

// Scratch bf16 buffers (device globals: allocation-free)
__device__ __align__(256) __nv_bfloat16 g_xb[(size_t)M_TOTAL * K_TOTAL];
__device__ __align__(256) __nv_bfloat16 g_bt[(size_t)N_TOTAL * K_TOTAL];

// ---------------------------------------------------------------------------
// Helpers
// ---------------------------------------------------------------------------
__device__ __forceinline__ uint32_t smem_u32(const void* p) {
    uint32_t a;
    asm("{ .reg .u64 t; cvta.to.shared.u64 t, %1; cvt.u32.u64 %0, t; }" : "=r"(a) : "l"(p));
    return a;
}
__device__ __forceinline__ uint32_t sw128(uint32_t off) {
    return off ^ ((off >> 3) & 0x70);
}
__device__ __forceinline__ void cp_async16(uint32_t smem_addr, const void* gptr) {
    asm volatile("cp.async.cg.shared.global [%0], [%1], 16;"
                 :: "r"(smem_addr), "l"(gptr) : "memory");
}
#define CP_COMMIT() asm volatile("cp.async.commit_group;" ::: "memory")
#define CP_WAIT(n)  asm volatile("cp.async.wait_group %0;" :: "n"(n) : "memory")

__device__ __forceinline__ void ldsm_x4(uint32_t* r, uint32_t addr) {
    asm volatile("ldmatrix.sync.aligned.m8n8.x4.shared.b16 {%0, %1, %2, %3}, [%4];"
                 : "=r"(r[0]), "=r"(r[1]), "=r"(r[2]), "=r"(r[3]) : "r"(addr));
}
__device__ __forceinline__ void mma16816(float* c, const uint32_t* a, const uint32_t* b) {
    asm volatile("mma.sync.aligned.m16n8k16.row.col.f32.bf16.bf16.f32 "
                 "{%0, %1, %2, %3}, {%4, %5, %6, %7}, {%8, %9}, {%0, %1, %2, %3};"
                 : "+f"(c[0]), "+f"(c[1]), "+f"(c[2]), "+f"(c[3])
                 : "r"(a[0]), "r"(a[1]), "r"(a[2]), "r"(a[3]), "r"(b[0]), "r"(b[1]));
}
__device__ __forceinline__ uint32_t pack_bf16x2(float a, float b) {
    __nv_bfloat162 h = __floats2bfloat162_rn(a, b);
    return *reinterpret_cast<uint32_t*>(&h);
}

// ---------------------------------------------------------------------------
// Fused conversion kernel:
//   blocks [0, 8192):         x fp32 -> g_xb bf16 (8 elems/thread)
//   blocks [8192, 8192+1024): matrix[K,N] -> g_bt[N,K] bf16 (32x32 tiles)
// ---------------------------------------------------------------------------
#define CVT_X_BLOCKS (M_TOTAL * K_TOTAL / (256 * 8))   // 8192
#define CVT_T_BLOCKS ((K_TOTAL / 32) * (N_TOTAL / 32)) // 1024

__global__ void __launch_bounds__(256)
cvt_kernel(const float* __restrict__ x, const float* __restrict__ m) {
    int tid = threadIdx.x;
    if (blockIdx.x < CVT_X_BLOCKS) {
        size_t i = ((size_t)blockIdx.x * 256 + tid) * 8;
        float4 a = *reinterpret_cast<const float4*>(x + i);
        float4 b = *reinterpret_cast<const float4*>(x + i + 4);
        uint4 o;
        o.x = pack_bf16x2(a.x, a.y);
        o.y = pack_bf16x2(a.z, a.w);
        o.z = pack_bf16x2(b.x, b.y);
        o.w = pack_bf16x2(b.z, b.w);
        *reinterpret_cast<uint4*>(g_xb + i) = o;
    } else {
        __shared__ float tile[32][33];
        int t = blockIdx.x - CVT_X_BLOCKS;
        int bn = (t & 31) * 32;          // n block
        int bk = (t >> 5) * 32;          // k block
        int lane = tid & 31;
        int rr = tid >> 5;               // 0..7
#pragma unroll
        for (int i = 0; i < 4; i++) {
            int row = i * 8 + rr;        // k within tile
            tile[row][lane] = m[(size_t)(bk + row) * N_TOTAL + bn + lane];
        }
        __syncthreads();
#pragma unroll
        for (int i = 0; i < 4; i++) {
            int row = i * 8 + rr;        // n within tile
            g_bt[(size_t)(bn + row) * K_TOTAL + bk + lane] =
                __float2bfloat16_rn(tile[lane][row]);
        }
    }
}

// ---------------------------------------------------------------------------
// GEMM + log kernel (persistent, cross-tile pipelined, SM-balanced tiles)
// ---------------------------------------------------------------------------
// Issue cp.asyncs for global chunk g of this CTA's contiguous tile range.
__device__ __forceinline__ void issue_chunk(uint32_t smem_base, int g, int t_begin, int tid) {
    int t = t_begin + (g >> 4);          // contiguous tiles
    int kc = g & (NCHUNK - 1);
    int m0 = (t >> 3) * TILE_M;          // t = m_idx*8 + n_idx
    int n0 = (t & 7) * TILE_N;
    const uint4* Ag = reinterpret_cast<const uint4*>(g_xb + (size_t)m0 * K_TOTAL + kc * BK);
    const uint4* Bg = reinterpret_cast<const uint4*>(g_bt + (size_t)n0 * K_TOTAL + kc * BK);
    uint32_t Abase = smem_base + SMEM_PAD + (g % NSTAGE) * BUF_STRIDE;
    uint32_t Bbase = Abase + TILE_BYTES;
#pragma unroll
    for (int i = 0; i < 4; i++) {
        int cc = i * 256 + tid;           // 1024 16B-chunks per tile
        int row = cc >> 3;                // 0..127
        int c16 = cc & 7;                 // 16B chunk within 128B row
        uint32_t sw = sw128((uint32_t)(row * 128 + c16 * 16));
        cp_async16(Abase + sw, Ag + (size_t)row * (K_TOTAL / 8) + c16);
        cp_async16(Bbase + sw, Bg + (size_t)row * (K_TOTAL / 8) + c16);
    }
    CP_COMMIT();
}

__global__ void __launch_bounds__(256, 2)
logmm_gemm_kernel(float* __restrict__ out) {
    extern __shared__ char smem[];
    uint32_t sb = smem_u32(smem);
    int tid = threadIdx.x;
    int wid = tid >> 5;
    int lid = tid & 31;

    // 8 warps: warp_m in {0,1} (64 rows), warp_n in {0..3} (32 cols)
    int warp_m = wid >> 2;
    int warp_n = wid & 3;

    // SM-balanced contiguous assignment: CTAs b and b+148 share an SM
    // (classic-launch LUT[bid%148]). 1024 tiles = 136 SMs x 7 + 12 SMs x 6.
    int s = blockIdx.x % NSM;        // SM index
    int slot = blockIdx.x / NSM;     // 0 or 1 within the SM pair
    int tiles_s = (s < 136) ? 7 : 6;
    int start_s = (s < 136) ? 7 * s : (7 * 136 + 6 * (s - 136));
    int half = (tiles_s + 1) >> 1;   // slot0: 4 (or 3), slot1: 3
    int t_begin = start_s + (slot ? half : 0);
    int my_tiles = slot ? (tiles_s - half) : half;
    int G = my_tiles * NCHUNK;

    float acc[4][4][4];
#pragma unroll
    for (int mf = 0; mf < 4; mf++)
#pragma unroll
        for (int nf = 0; nf < 4; nf++)
#pragma unroll
            for (int i = 0; i < 4; i++) acc[mf][nf][i] = 0.0f;

    // Prologue: fill 2 of 3 stages
    issue_chunk(sb, 0, t_begin, tid);
    issue_chunk(sb, 1, t_begin, tid);

    for (int g = 0; g < G; g++) {
        if (g == G - 1) { CP_WAIT(0); } else { CP_WAIT(1); }
        __syncthreads();

        // Prefetch chunk g+2 (may belong to the NEXT tile -> no drain)
        if (g + 2 < G) issue_chunk(sb, g + 2, t_begin, tid);

        uint32_t Ab = sb + SMEM_PAD + (g % NSTAGE) * BUF_STRIDE;
        uint32_t Bb = Ab + TILE_BYTES;
#pragma unroll
        for (int ks = 0; ks < 4; ks++) {
            uint32_t a[4][4], b[2][4];
#pragma unroll
            for (int mf = 0; mf < 4; mf++) {
                int row = warp_m * 64 + mf * 16 + (lid & 15);
                uint32_t off = (uint32_t)(row * 128 + ks * 32 + ((lid >> 4) << 4));
                ldsm_x4(a[mf], Ab + sw128(off));
            }
#pragma unroll
            for (int p = 0; p < 2; p++) {
                int row = warp_n * 32 + p * 16 + (lid & 7) + ((lid >> 4) << 3);
                uint32_t off = (uint32_t)(row * 128 + ks * 32 + (((lid >> 3) & 1) << 4));
                ldsm_x4(b[p], Bb + sw128(off));
            }
#pragma unroll
            for (int mf = 0; mf < 4; mf++)
#pragma unroll
                for (int nf = 0; nf < 4; nf++)
                    mma16816(acc[mf][nf], a[mf], b[nf >> 1] + (nf & 1) * 2);
        }

        // Tile finished? Epilogue overlapped with in-flight next-tile loads.
        if ((g & (NCHUNK - 1)) == NCHUNK - 1) {
            int t = t_begin + (g >> 4);
            int m0 = (t >> 3) * TILE_M;
            int n0 = (t & 7) * TILE_N;
#pragma unroll
            for (int mf = 0; mf < 4; mf++) {
#pragma unroll
                for (int nf = 0; nf < 4; nf++) {
                    int row0 = m0 + warp_m * 64 + mf * 16 + (lid >> 2);
                    int col = n0 + warp_n * 32 + nf * 8 + (lid & 3) * 2;
                    float2 v0, v1;
                    v0.x = __logf(fmaxf(acc[mf][nf][0], 1.17549435e-38f));
                    v0.y = __logf(fmaxf(acc[mf][nf][1], 1.17549435e-38f));
                    v1.x = __logf(fmaxf(acc[mf][nf][2], 1.17549435e-38f));
                    v1.y = __logf(fmaxf(acc[mf][nf][3], 1.17549435e-38f));
                    *reinterpret_cast<float2*>(out + (size_t)row0 * N_TOTAL + col) = v0;
                    *reinterpret_cast<float2*>(out + (size_t)(row0 + 8) * N_TOTAL + col) = v1;
                    acc[mf][nf][0] = 0.0f;
                    acc[mf][nf][1] = 0.0f;
                    acc[mf][nf][2] = 0.0f;
                    acc[mf][nf][3] = 0.0f;
                }
            }
        }
    }
}

// ---------------------------------------------------------------------------
// Launch
// ---------------------------------------------------------------------------
extern "C" void kernel_launch(void* const* d_in, const int* in_sizes, int n_in,
                              void* d_out, int out_size) {
    const float* x = (const float*)d_in[0];
    const float* mat = (const float*)d_in[1];
    if (n_in >= 2 && in_sizes[0] == N_TOTAL * K_TOTAL && in_sizes[1] == M_TOTAL * K_TOTAL) {
        const float* t = x; x = mat; mat = t;
    }
    float* out = (float*)d_out;

    cudaFuncSetAttribute(logmm_gemm_kernel,
                         cudaFuncAttributeMaxDynamicSharedMemorySize, SMEM_TOTAL);

    cvt_kernel<<<CVT_X_BLOCKS + CVT_T_BLOCKS, 256>>>(x, mat);
    logmm_gemm_kernel<<<GRID_GEMM, 256, SMEM_TOTAL>>>(out);
}